// round 5
// baseline (speedup 1.0000x reference)
#include <cuda_runtime.h>
#include <cuda_bf16.h>

// Problem constants
#define Bq  2
#define Nq  2048
#define Dq  1024
#define Hq  8
#define DHq 128
#define BHq 16            // B*H
#define MROWS (Bq*Nq)     // 4096

// Scratch (device globals: allocation-free rule)
__device__ float g_qkv[(size_t)MROWS * 3 * Dq];   // [b*n, 3072]   50 MB
__device__ float g_qp [(size_t)BHq * Nq * DHq];   // [bh, n, 128]  16 MB
__device__ float g_kp [(size_t)BHq * Nq * DHq];
__device__ float g_vp [(size_t)BHq * Nq * DHq];
__device__ float g_M  [(size_t)BHq * DHq * DHq];  // [bh, 128, 128] 1 MB
__device__ float g_of [(size_t)MROWS * Dq];       // [b*n, 1024]   16 MB

// ---------------------------------------------------------------------------
// NT SGEMM body: C[M,N] = A[M,K] @ B[N,K]^T + bias[N]
// BM=BN=128, BK=8, 256 threads, 8x8 microtile per thread.
// Requires M,N,K multiples of 128/128/8 (true for all our shapes).
// ---------------------------------------------------------------------------
__device__ __forceinline__ void gemm_nt_body(
    const float* __restrict__ A, const float* __restrict__ B,
    const float* __restrict__ bias, float* __restrict__ C,
    int N, int K)
{
    __shared__ float As[8][128];
    __shared__ float Bs[8][128];
    const int tid     = threadIdx.x;
    const int rowBase = blockIdx.y * 128;
    const int colBase = blockIdx.x * 128;
    const int aRow = tid >> 1;          // 0..127
    const int aK   = (tid & 1) << 2;    // 0 or 4
    const int tm0  = (tid >> 4) << 3;   // row microtile origin
    const int tn0  = (tid & 15) << 3;   // col microtile origin

    float acc[8][8];
    #pragma unroll
    for (int i = 0; i < 8; i++)
        #pragma unroll
        for (int j = 0; j < 8; j++) acc[i][j] = 0.f;

    for (int k0 = 0; k0 < K; k0 += 8) {
        float4 a4 = *(const float4*)(A + (size_t)(rowBase + aRow) * K + k0 + aK);
        float4 b4 = *(const float4*)(B + (size_t)(colBase + aRow) * K + k0 + aK);
        As[aK + 0][aRow] = a4.x; As[aK + 1][aRow] = a4.y;
        As[aK + 2][aRow] = a4.z; As[aK + 3][aRow] = a4.w;
        Bs[aK + 0][aRow] = b4.x; Bs[aK + 1][aRow] = b4.y;
        Bs[aK + 2][aRow] = b4.z; Bs[aK + 3][aRow] = b4.w;
        __syncthreads();
        #pragma unroll
        for (int kk = 0; kk < 8; kk++) {
            float4 ra0 = *(const float4*)&As[kk][tm0];
            float4 ra1 = *(const float4*)&As[kk][tm0 + 4];
            float4 rb0 = *(const float4*)&Bs[kk][tn0];
            float4 rb1 = *(const float4*)&Bs[kk][tn0 + 4];
            float ra[8] = {ra0.x, ra0.y, ra0.z, ra0.w, ra1.x, ra1.y, ra1.z, ra1.w};
            float rb[8] = {rb0.x, rb0.y, rb0.z, rb0.w, rb1.x, rb1.y, rb1.z, rb1.w};
            #pragma unroll
            for (int i = 0; i < 8; i++)
                #pragma unroll
                for (int j = 0; j < 8; j++)
                    acc[i][j] += ra[i] * rb[j];
        }
        __syncthreads();
    }

    #pragma unroll
    for (int i = 0; i < 8; i++) {
        const size_t r = (size_t)(rowBase + tm0 + i);
        #pragma unroll
        for (int j = 0; j < 8; j += 4) {
            float4 v;
            v.x = acc[i][j + 0] + bias[colBase + tn0 + j + 0];
            v.y = acc[i][j + 1] + bias[colBase + tn0 + j + 1];
            v.z = acc[i][j + 2] + bias[colBase + tn0 + j + 2];
            v.w = acc[i][j + 3] + bias[colBase + tn0 + j + 3];
            *(float4*)(C + r * N + colBase + tn0 + j) = v;
        }
    }
}

// GEMM1: qkv = x @ w_qkv^T + b_qkv   -> g_qkv   (grid 24 x 32)
__global__ __launch_bounds__(256) void k_gemm_qkv(
    const float* __restrict__ x, const float* __restrict__ w,
    const float* __restrict__ b)
{
    gemm_nt_body(x, w, b, g_qkv, 3 * Dq, Dq);
}

// GEMM3: out = g_of @ w_o^T + b_o    (grid 8 x 32)
__global__ __launch_bounds__(256) void k_gemm_out(
    const float* __restrict__ w, const float* __restrict__ b,
    float* __restrict__ out)
{
    gemm_nt_body(g_of, w, b, out, Dq, Dq);
}

// ---------------------------------------------------------------------------
// Repack: qkv[b,n, k*1024 + d*8 + h] -> {q,k,v}pack[(b*8+h), n, d]
// One block per (b,n) row. Read coalesced, permute in smem, write coalesced.
// ---------------------------------------------------------------------------
__global__ __launch_bounds__(256) void k_repack()
{
    __shared__ float row[3 * Dq];
    const int bn = blockIdx.x;                 // b*2048 + n
    const float* src = g_qkv + (size_t)bn * (3 * Dq);
    for (int i = threadIdx.x; i < 3 * Dq; i += 256) row[i] = src[i];
    __syncthreads();
    const int b = bn >> 11;
    const int n = bn & 2047;
    for (int i = threadIdx.x; i < 3 * Dq; i += 256) {
        const int kk = i >> 10;
        const int r  = i & 1023;
        const int h  = r >> 7;                 // dest-ordered: d contiguous
        const int d  = r & 127;
        const float v = row[kk * 1024 + d * 8 + h];
        const size_t dst = ((size_t)((b * 8 + h) * Nq + n)) * DHq + d;
        if      (kk == 0) g_qp[dst] = v;
        else if (kk == 1) g_kp[dst] = v;
        else              g_vp[dst] = v;
    }
}

// Zero g_M before atomic reduction (grid 1024 x 256)
__global__ void k_zeroM()
{
    const int i = blockIdx.x * blockDim.x + threadIdx.x;
    if (i < BHq * DHq * DHq) g_M[i] = 0.f;
}

// ---------------------------------------------------------------------------
// M[bh] = K^T @ V  (contraction over n), split 8-way over n + atomicAdd.
// grid (16, 8), 256 threads, 8x8 microtile over the 128x128 output.
// ---------------------------------------------------------------------------
__global__ __launch_bounds__(256) void k_ktv()
{
    __shared__ float Ks[8][128];
    __shared__ float Vs[8][128];
    const int bh  = blockIdx.x;
    const int n0  = blockIdx.y * 256;
    const int tid = threadIdx.x;
    const int lr  = tid >> 5;                  // 0..7 (n row in tile)
    const int lc  = (tid & 31) << 2;           // col*4
    const int tm0 = (tid >> 4) << 3;           // d1 microtile origin
    const int tn0 = (tid & 15) << 3;           // d2 microtile origin
    const float* kp = g_kp + (size_t)bh * Nq * DHq;
    const float* vp = g_vp + (size_t)bh * Nq * DHq;

    float acc[8][8];
    #pragma unroll
    for (int i = 0; i < 8; i++)
        #pragma unroll
        for (int j = 0; j < 8; j++) acc[i][j] = 0.f;

    for (int nt = 0; nt < 256; nt += 8) {
        const size_t nrow = (size_t)(n0 + nt + lr);
        *(float4*)&Ks[lr][lc] = *(const float4*)(kp + nrow * DHq + lc);
        *(float4*)&Vs[lr][lc] = *(const float4*)(vp + nrow * DHq + lc);
        __syncthreads();
        #pragma unroll
        for (int kk = 0; kk < 8; kk++) {
            float4 ra0 = *(const float4*)&Ks[kk][tm0];
            float4 ra1 = *(const float4*)&Ks[kk][tm0 + 4];
            float4 rb0 = *(const float4*)&Vs[kk][tn0];
            float4 rb1 = *(const float4*)&Vs[kk][tn0 + 4];
            float ra[8] = {ra0.x, ra0.y, ra0.z, ra0.w, ra1.x, ra1.y, ra1.z, ra1.w};
            float rb[8] = {rb0.x, rb0.y, rb0.z, rb0.w, rb1.x, rb1.y, rb1.z, rb1.w};
            #pragma unroll
            for (int i = 0; i < 8; i++)
                #pragma unroll
                for (int j = 0; j < 8; j++)
                    acc[i][j] += ra[i] * rb[j];
        }
        __syncthreads();
    }

    float* Mp = g_M + (size_t)bh * DHq * DHq;
    #pragma unroll
    for (int i = 0; i < 8; i++)
        #pragma unroll
        for (int j = 0; j < 8; j++)
            atomicAdd(&Mp[(tm0 + i) * DHq + tn0 + j], acc[i][j]);
}

// ---------------------------------------------------------------------------
// O = Q @ M  (NN GEMM, K=128). Writes g_of in 'b n (h d)' layout directly.
// grid (16 bh, 16 n-tiles), 256 threads, 8x8 microtile.
// ---------------------------------------------------------------------------
__global__ __launch_bounds__(256) void k_qm()
{
    __shared__ float Qs[8][128];
    __shared__ float Ms[8][128];
    const int bh  = blockIdx.x;
    const int n0  = blockIdx.y * 128;
    const int tid = threadIdx.x;
    const int aRow = tid >> 1;                 // 0..127 (n row)
    const int aK   = (tid & 1) << 2;           // 0 or 4
    const int br   = tid >> 5;                 // 0..7  (M row in BK)
    const int bc   = (tid & 31) << 2;          // col*4
    const int tm0  = (tid >> 4) << 3;
    const int tn0  = (tid & 15) << 3;
    const float* qp = g_qp + (size_t)bh * Nq * DHq;
    const float* Mp = g_M  + (size_t)bh * DHq * DHq;

    float acc[8][8];
    #pragma unroll
    for (int i = 0; i < 8; i++)
        #pragma unroll
        for (int j = 0; j < 8; j++) acc[i][j] = 0.f;

    for (int k0 = 0; k0 < DHq; k0 += 8) {
        float4 q4 = *(const float4*)(qp + (size_t)(n0 + aRow) * DHq + k0 + aK);
        Qs[aK + 0][aRow] = q4.x; Qs[aK + 1][aRow] = q4.y;
        Qs[aK + 2][aRow] = q4.z; Qs[aK + 3][aRow] = q4.w;
        *(float4*)&Ms[br][bc] = *(const float4*)(Mp + (k0 + br) * DHq + bc);
        __syncthreads();
        #pragma unroll
        for (int kk = 0; kk < 8; kk++) {
            float4 ra0 = *(const float4*)&Qs[kk][tm0];
            float4 ra1 = *(const float4*)&Qs[kk][tm0 + 4];
            float4 rb0 = *(const float4*)&Ms[kk][tn0];
            float4 rb1 = *(const float4*)&Ms[kk][tn0 + 4];
            float ra[8] = {ra0.x, ra0.y, ra0.z, ra0.w, ra1.x, ra1.y, ra1.z, ra1.w};
            float rb[8] = {rb0.x, rb0.y, rb0.z, rb0.w, rb1.x, rb1.y, rb1.z, rb1.w};
            #pragma unroll
            for (int i = 0; i < 8; i++)
                #pragma unroll
                for (int j = 0; j < 8; j++)
                    acc[i][j] += ra[i] * rb[j];
        }
        __syncthreads();
    }

    const int b = bh >> 3;
    const int h = bh & 7;
    #pragma unroll
    for (int i = 0; i < 8; i++) {
        const int n = n0 + tm0 + i;
        float* dst = g_of + ((size_t)(b * Nq + n)) * Dq + h * DHq + tn0;
        #pragma unroll
        for (int j = 0; j < 8; j += 4) {
            float4 v = make_float4(acc[i][j], acc[i][j + 1], acc[i][j + 2], acc[i][j + 3]);
            *(float4*)(dst + j) = v;
        }
    }
}

// ---------------------------------------------------------------------------
extern "C" void kernel_launch(void* const* d_in, const int* in_sizes, int n_in,
                              void* d_out, int out_size)
{
    const float* x     = (const float*)d_in[0];   // [2,2048,1024]
    const float* w_qkv = (const float*)d_in[1];   // [3072,1024]
    const float* b_qkv = (const float*)d_in[2];   // [3072]
    const float* w_o   = (const float*)d_in[3];   // [1024,1024]
    const float* b_o   = (const float*)d_in[4];   // [1024]
    float* out = (float*)d_out;                   // [2,2048,1024]

    // 1. QKV projection
    k_gemm_qkv<<<dim3(3 * Dq / 128, MROWS / 128), 256>>>(x, w_qkv, b_qkv);
    // 2. Repack into per-head contiguous q/k/v
    k_repack<<<MROWS, 256>>>();
    // 3. M = K^T V (zero + split-n atomic reduce)
    k_zeroM<<<(BHq * DHq * DHq + 255) / 256, 256>>>();
    k_ktv<<<dim3(BHq, 8), 256>>>();
    // 4. O = Q M, written as [b, n, (h d)]
    k_qm<<<dim3(BHq, Nq / 128), 256>>>();
    // 5. Output projection
    k_gemm_out<<<dim3(Dq / 128, MROWS / 128), 256>>>(w_o, b_o, out);
}

// round 17
// speedup vs baseline: 2.6002x; 2.6002x over previous
#include <cuda_runtime.h>
#include <cuda_bf16.h>
#include <cstdint>

// Problem constants
#define Bq  2
#define Nq  2048
#define Dq  1024
#define Hq  8
#define DHq 128
#define BHq 16            // B*H
#define MROWS (Bq*Nq)     // 4096

// ---------------------------------------------------------------------------
// Scratch (device globals: allocation-free rule)
// ---------------------------------------------------------------------------
__device__ float g_qkv[(size_t)MROWS * 3 * Dq];          // [4096, 3072] fp32
__device__ float g_qp [(size_t)BHq * Nq * DHq];          // [bh, n, 128]
__device__ float g_kp [(size_t)BHq * Nq * DHq];
__device__ float g_vp [(size_t)BHq * Nq * DHq];
__device__ float g_M  [(size_t)BHq * DHq * DHq];         // [bh, 128, 128]

__device__ __align__(128) __nv_bfloat16 g_x_hi [(size_t)MROWS * Dq];
__device__ __align__(128) __nv_bfloat16 g_x_lo [(size_t)MROWS * Dq];
__device__ __align__(128) __nv_bfloat16 g_wq_hi[(size_t)3 * Dq * Dq];
__device__ __align__(128) __nv_bfloat16 g_wq_lo[(size_t)3 * Dq * Dq];
__device__ __align__(128) __nv_bfloat16 g_wo_hi[(size_t)Dq * Dq];
__device__ __align__(128) __nv_bfloat16 g_wo_lo[(size_t)Dq * Dq];
__device__ __align__(128) __nv_bfloat16 g_of_hi[(size_t)MROWS * Dq];
__device__ __align__(128) __nv_bfloat16 g_of_lo[(size_t)MROWS * Dq];

// ---------------------------------------------------------------------------
// PTX helpers (baseline sm_80+/sm_90 features only -- NO arch-'a' features)
// ---------------------------------------------------------------------------
__device__ __forceinline__ uint32_t smem_u32(const void* p) {
    uint32_t a;
    asm("{ .reg .u64 t; cvta.to.shared.u64 t, %1; cvt.u32.u64 %0, t; }" : "=r"(a) : "l"(p));
    return a;
}

#define SW128(o) ((o) ^ (((o) >> 3) & 0x70))

#define CP_ASYNC16(saddr, gptr) \
    asm volatile("cp.async.cg.shared.global [%0], [%1], 16;" :: "r"(saddr), "l"(gptr))
#define CP_COMMIT() asm volatile("cp.async.commit_group;" ::: "memory")
#define CP_WAIT(n)  asm volatile("cp.async.wait_group %0;" :: "n"(n) : "memory")

__device__ __forceinline__ void ldm_x4(uint32_t* r, uint32_t addr) {
    asm volatile("ldmatrix.sync.aligned.m8n8.x4.shared.b16 {%0,%1,%2,%3}, [%4];"
                 : "=r"(r[0]), "=r"(r[1]), "=r"(r[2]), "=r"(r[3]) : "r"(addr));
}

__device__ __forceinline__ void mma_bf16(float* d, const uint32_t* a, const uint32_t* b) {
    asm volatile(
        "mma.sync.aligned.m16n8k16.row.col.f32.bf16.bf16.f32 "
        "{%0,%1,%2,%3}, {%4,%5,%6,%7}, {%8,%9}, {%0,%1,%2,%3};"
        : "+f"(d[0]), "+f"(d[1]), "+f"(d[2]), "+f"(d[3])
        : "r"(a[0]), "r"(a[1]), "r"(a[2]), "r"(a[3]), "r"(b[0]), "r"(b[1]));
}

// ---------------------------------------------------------------------------
// fp32 -> (bf16 hi, bf16 lo) split
// ---------------------------------------------------------------------------
__global__ void k_cvt(const float* __restrict__ s, __nv_bfloat16* __restrict__ hi,
                      __nv_bfloat16* __restrict__ lo, int n)
{
    int i = blockIdx.x * 256 + threadIdx.x;
    if (i < n) {
        float v = s[i];
        __nv_bfloat16 h = __float2bfloat16(v);
        hi[i] = h;
        lo[i] = __float2bfloat16(v - __bfloat162float(h));
    }
}

// ---------------------------------------------------------------------------
// mma.sync bf16x3 NT GEMM: C[M,N] = Ahi*Bhi^T + Ahi*Blo^T + Alo*Bhi^T + bias
// A: [M,K] K-major, B: [N,K] K-major. Tile: 128x128, BK=64 bf16.
// 2-stage cp.async pipeline. 8 warps = 4(M) x 2(N), warp tile 32x64.
// SMEM tiles: 128 rows x 128B (SW128 swizzled).
// ---------------------------------------------------------------------------
#define STAGE_BYTES 65536
#define GEMM_SMEM_BYTES (2 * STAGE_BYTES)
#define SM_AH(s)  ((s) * STAGE_BYTES)
#define SM_AL(s)  (SM_AH(s) + 16384)
#define SM_BH(s)  (SM_AH(s) + 32768)
#define SM_BL(s)  (SM_AH(s) + 49152)

__device__ __forceinline__ void load_tile_async(
    const __nv_bfloat16* __restrict__ g, int K, int kt, uint32_t s_tile, int tid)
{
    #pragma unroll
    for (int r = 0; r < 4; r++) {
        const int idx = tid + r * 256;
        const int row = idx >> 3, c16 = idx & 7;
        const __nv_bfloat16* gp = g + (size_t)row * K + kt * 64 + c16 * 8;
        const uint32_t so = s_tile + SW128((uint32_t)(row * 128 + c16 * 16));
        CP_ASYNC16(so, gp);
    }
}

__global__ __launch_bounds__(256, 1) void k_gemm_tc(
    const __nv_bfloat16* __restrict__ Ahi, const __nv_bfloat16* __restrict__ Alo,
    const __nv_bfloat16* __restrict__ Bhi, const __nv_bfloat16* __restrict__ Blo,
    const float* __restrict__ bias, float* __restrict__ C,
    int N, int K)
{
    extern __shared__ __align__(1024) char smem[];
    const uint32_t sb = smem_u32(smem);
    const int tid  = threadIdx.x;
    const int lane = tid & 31;
    const int w    = tid >> 5;
    const int wm   = w & 3;          // 4 M-warps
    const int wn   = w >> 2;         // 2 N-warps
    const int rowBase = blockIdx.y * 128;
    const int colBase = blockIdx.x * 128;

    const __nv_bfloat16* Ah = Ahi + (size_t)rowBase * K;
    const __nv_bfloat16* Al = Alo + (size_t)rowBase * K;
    const __nv_bfloat16* Bh = Bhi + (size_t)colBase * K;
    const __nv_bfloat16* Bl = Blo + (size_t)colBase * K;

    float acc[2][8][4];
    #pragma unroll
    for (int mi = 0; mi < 2; mi++)
        #pragma unroll
        for (int ni = 0; ni < 8; ni++)
            #pragma unroll
            for (int e = 0; e < 4; e++) acc[mi][ni][e] = 0.f;

    const int KC = K >> 6;

    // prologue: stage 0
    load_tile_async(Ah, K, 0, sb + SM_AH(0), tid);
    load_tile_async(Al, K, 0, sb + SM_AL(0), tid);
    load_tile_async(Bh, K, 0, sb + SM_BH(0), tid);
    load_tile_async(Bl, K, 0, sb + SM_BL(0), tid);
    CP_COMMIT();

    // precomputed ldmatrix intra-tile offsets (depend only on lane)
    const int aRowL = (lane & 15);
    const int aColL = (lane >> 4) * 8;
    const int bRowL = (lane & 7) + (lane >> 4) * 8;
    const int bColL = ((lane >> 3) & 1) * 8;

    for (int kt = 0; kt < KC; kt++) {
        const int s = kt & 1;
        if (kt + 1 < KC) {
            const int s2 = (kt + 1) & 1;
            load_tile_async(Ah, K, kt + 1, sb + SM_AH(s2), tid);
            load_tile_async(Al, K, kt + 1, sb + SM_AL(s2), tid);
            load_tile_async(Bh, K, kt + 1, sb + SM_BH(s2), tid);
            load_tile_async(Bl, K, kt + 1, sb + SM_BL(s2), tid);
            CP_COMMIT();
            CP_WAIT(1);
        } else {
            CP_WAIT(0);
        }
        __syncthreads();

        const uint32_t sAh = sb + SM_AH(s), sAl = sb + SM_AL(s);
        const uint32_t sBh = sb + SM_BH(s), sBl = sb + SM_BL(s);

        #pragma unroll
        for (int ks = 0; ks < 4; ks++) {
            uint32_t ah[2][4], al[2][4];
            #pragma unroll
            for (int mi = 0; mi < 2; mi++) {
                const int row = wm * 32 + mi * 16 + aRowL;
                const int col = ks * 16 + aColL;
                const uint32_t off = SW128((uint32_t)(row * 128 + col * 2));
                ldm_x4(ah[mi], sAh + off);
                ldm_x4(al[mi], sAl + off);
            }
            uint32_t bh[8][2], bl[8][2];
            #pragma unroll
            for (int np = 0; np < 4; np++) {
                const int nrow = wn * 64 + np * 16 + bRowL;
                const int col  = ks * 16 + bColL;
                const uint32_t off = SW128((uint32_t)(nrow * 128 + col * 2));
                uint32_t t[4];
                ldm_x4(t, sBh + off);
                bh[np * 2][0] = t[0]; bh[np * 2][1] = t[1];
                bh[np * 2 + 1][0] = t[2]; bh[np * 2 + 1][1] = t[3];
                ldm_x4(t, sBl + off);
                bl[np * 2][0] = t[0]; bl[np * 2][1] = t[1];
                bl[np * 2 + 1][0] = t[2]; bl[np * 2 + 1][1] = t[3];
            }
            #pragma unroll
            for (int mi = 0; mi < 2; mi++)
                #pragma unroll
                for (int ni = 0; ni < 8; ni++) {
                    mma_bf16(acc[mi][ni], ah[mi], bh[ni]);
                    mma_bf16(acc[mi][ni], ah[mi], bl[ni]);
                    mma_bf16(acc[mi][ni], al[mi], bh[ni]);
                }
        }
        __syncthreads();
    }

    // epilogue: c frag layout -> gmem fp32 + bias
    const int qr = lane >> 2;            // 0..7
    const int qc = (lane & 3) * 2;       // 0,2,4,6
    #pragma unroll
    for (int mi = 0; mi < 2; mi++) {
        const int row0 = rowBase + wm * 32 + mi * 16 + qr;
        #pragma unroll
        for (int ni = 0; ni < 8; ni++) {
            const int col = colBase + wn * 64 + ni * 8 + qc;
            const float2 b2 = *(const float2*)(bias + col);
            float2 v0, v1;
            v0.x = acc[mi][ni][0] + b2.x;  v0.y = acc[mi][ni][1] + b2.y;
            v1.x = acc[mi][ni][2] + b2.x;  v1.y = acc[mi][ni][3] + b2.y;
            *(float2*)(C + (size_t)row0 * N + col)       = v0;
            *(float2*)(C + (size_t)(row0 + 8) * N + col) = v1;
        }
    }
}

// ---------------------------------------------------------------------------
// Repack: qkv[b,n, k*1024 + d*8 + h] -> {q,k,v}pack[(b*8+h), n, d]
// ---------------------------------------------------------------------------
__global__ __launch_bounds__(256) void k_repack()
{
    __shared__ float row[3 * Dq];
    const int bn = blockIdx.x;
    const float* src = g_qkv + (size_t)bn * (3 * Dq);
    for (int i = threadIdx.x; i < 3 * Dq; i += 256) row[i] = src[i];
    __syncthreads();
    const int b = bn >> 11;
    const int n = bn & 2047;
    for (int i = threadIdx.x; i < 3 * Dq; i += 256) {
        const int kk = i >> 10;
        const int r  = i & 1023;
        const int h  = r >> 7;
        const int d  = r & 127;
        const float v = row[kk * 1024 + d * 8 + h];
        const size_t dst = ((size_t)((b * 8 + h) * Nq + n)) * DHq + d;
        if      (kk == 0) g_qp[dst] = v;
        else if (kk == 1) g_kp[dst] = v;
        else              g_vp[dst] = v;
    }
}

__global__ void k_zeroM()
{
    const int i = blockIdx.x * blockDim.x + threadIdx.x;
    if (i < BHq * DHq * DHq) g_M[i] = 0.f;
}

// ---------------------------------------------------------------------------
// M[bh] = K^T @ V, split 16-way over n + atomicAdd (grid 16x16)
// ---------------------------------------------------------------------------
__global__ __launch_bounds__(256) void k_ktv()
{
    __shared__ float Ks[8][128];
    __shared__ float Vs[8][128];
    const int bh  = blockIdx.x;
    const int n0  = blockIdx.y * 128;
    const int tid = threadIdx.x;
    const int lr  = tid >> 5;
    const int lc  = (tid & 31) << 2;
    const int tm0 = (tid >> 4) << 3;
    const int tn0 = (tid & 15) << 3;
    const float* kp = g_kp + (size_t)bh * Nq * DHq;
    const float* vp = g_vp + (size_t)bh * Nq * DHq;

    float acc[8][8];
    #pragma unroll
    for (int i = 0; i < 8; i++)
        #pragma unroll
        for (int j = 0; j < 8; j++) acc[i][j] = 0.f;

    for (int nt = 0; nt < 128; nt += 8) {
        const size_t nrow = (size_t)(n0 + nt + lr);
        *(float4*)&Ks[lr][lc] = *(const float4*)(kp + nrow * DHq + lc);
        *(float4*)&Vs[lr][lc] = *(const float4*)(vp + nrow * DHq + lc);
        __syncthreads();
        #pragma unroll
        for (int kk = 0; kk < 8; kk++) {
            float4 ra0 = *(const float4*)&Ks[kk][tm0];
            float4 ra1 = *(const float4*)&Ks[kk][tm0 + 4];
            float4 rb0 = *(const float4*)&Vs[kk][tn0];
            float4 rb1 = *(const float4*)&Vs[kk][tn0 + 4];
            float ra[8] = {ra0.x, ra0.y, ra0.z, ra0.w, ra1.x, ra1.y, ra1.z, ra1.w};
            float rb[8] = {rb0.x, rb0.y, rb0.z, rb0.w, rb1.x, rb1.y, rb1.z, rb1.w};
            #pragma unroll
            for (int i = 0; i < 8; i++)
                #pragma unroll
                for (int j = 0; j < 8; j++)
                    acc[i][j] += ra[i] * rb[j];
        }
        __syncthreads();
    }

    float* Mp = g_M + (size_t)bh * DHq * DHq;
    #pragma unroll
    for (int i = 0; i < 8; i++)
        #pragma unroll
        for (int j = 0; j < 8; j++)
            atomicAdd(&Mp[(tm0 + i) * DHq + tn0 + j], acc[i][j]);
}

// ---------------------------------------------------------------------------
// O = Q @ M (NN, K=128). Writes bf16 hi/lo of 'b n (h d)' output directly.
// ---------------------------------------------------------------------------
__global__ __launch_bounds__(256) void k_qm()
{
    __shared__ float Qs[8][128];
    __shared__ float Ms[8][128];
    const int bh  = blockIdx.x;
    const int n0  = blockIdx.y * 128;
    const int tid = threadIdx.x;
    const int aRow = tid >> 1;
    const int aK   = (tid & 1) << 2;
    const int br   = tid >> 5;
    const int bc   = (tid & 31) << 2;
    const int tm0  = (tid >> 4) << 3;
    const int tn0  = (tid & 15) << 3;
    const float* qp = g_qp + (size_t)bh * Nq * DHq;
    const float* Mp = g_M  + (size_t)bh * DHq * DHq;

    float acc[8][8];
    #pragma unroll
    for (int i = 0; i < 8; i++)
        #pragma unroll
        for (int j = 0; j < 8; j++) acc[i][j] = 0.f;

    for (int k0 = 0; k0 < DHq; k0 += 8) {
        float4 q4 = *(const float4*)(qp + (size_t)(n0 + aRow) * DHq + k0 + aK);
        Qs[aK + 0][aRow] = q4.x; Qs[aK + 1][aRow] = q4.y;
        Qs[aK + 2][aRow] = q4.z; Qs[aK + 3][aRow] = q4.w;
        *(float4*)&Ms[br][bc] = *(const float4*)(Mp + (k0 + br) * DHq + bc);
        __syncthreads();
        #pragma unroll
        for (int kk = 0; kk < 8; kk++) {
            float4 ra0 = *(const float4*)&Qs[kk][tm0];
            float4 ra1 = *(const float4*)&Qs[kk][tm0 + 4];
            float4 rb0 = *(const float4*)&Ms[kk][tn0];
            float4 rb1 = *(const float4*)&Ms[kk][tn0 + 4];
            float ra[8] = {ra0.x, ra0.y, ra0.z, ra0.w, ra1.x, ra1.y, ra1.z, ra1.w};
            float rb[8] = {rb0.x, rb0.y, rb0.z, rb0.w, rb1.x, rb1.y, rb1.z, rb1.w};
            #pragma unroll
            for (int i = 0; i < 8; i++)
                #pragma unroll
                for (int j = 0; j < 8; j++)
                    acc[i][j] += ra[i] * rb[j];
        }
        __syncthreads();
    }

    const int bb = bh >> 3;
    const int hh = bh & 7;
    #pragma unroll
    for (int i = 0; i < 8; i++) {
        const int n = n0 + tm0 + i;
        const size_t base = ((size_t)(bb * Nq + n)) * Dq + hh * DHq + tn0;
        #pragma unroll
        for (int j = 0; j < 8; j++) {
            const float v = acc[i][j];
            const __nv_bfloat16 h = __float2bfloat16(v);
            g_of_hi[base + j] = h;
            g_of_lo[base + j] = __float2bfloat16(v - __bfloat162float(h));
        }
    }
}

// ---------------------------------------------------------------------------
extern "C" void kernel_launch(void* const* d_in, const int* in_sizes, int n_in,
                              void* d_out, int out_size)
{
    const float* x     = (const float*)d_in[0];   // [2,2048,1024]
    const float* w_qkv = (const float*)d_in[1];   // [3072,1024]
    const float* b_qkv = (const float*)d_in[2];   // [3072]
    const float* w_o   = (const float*)d_in[3];   // [1024,1024]
    const float* b_o   = (const float*)d_in[4];   // [1024]
    float* out = (float*)d_out;                   // [2,2048,1024]

    cudaFuncSetAttribute(k_gemm_tc, cudaFuncAttributeMaxDynamicSharedMemorySize,
                         GEMM_SMEM_BYTES);

    __nv_bfloat16 *x_hi, *x_lo, *wq_hi, *wq_lo, *wo_hi, *wo_lo, *of_hi, *of_lo;
    cudaGetSymbolAddress((void**)&x_hi,  g_x_hi);
    cudaGetSymbolAddress((void**)&x_lo,  g_x_lo);
    cudaGetSymbolAddress((void**)&wq_hi, g_wq_hi);
    cudaGetSymbolAddress((void**)&wq_lo, g_wq_lo);
    cudaGetSymbolAddress((void**)&wo_hi, g_wo_hi);
    cudaGetSymbolAddress((void**)&wo_lo, g_wo_lo);
    cudaGetSymbolAddress((void**)&of_hi, g_of_hi);
    cudaGetSymbolAddress((void**)&of_lo, g_of_lo);
    float* qkv;
    cudaGetSymbolAddress((void**)&qkv, g_qkv);

    // 0. fp32 -> bf16 hi/lo splits
    k_cvt<<<(MROWS * Dq + 255) / 256, 256>>>(x, x_hi, x_lo, MROWS * Dq);
    k_cvt<<<(3 * Dq * Dq + 255) / 256, 256>>>(w_qkv, wq_hi, wq_lo, 3 * Dq * Dq);
    k_cvt<<<(Dq * Dq + 255) / 256, 256>>>(w_o, wo_hi, wo_lo, Dq * Dq);

    // 1. QKV projection (mma.sync bf16x3): [4096,3072] = x @ w_qkv^T + b
    k_gemm_tc<<<dim3(3 * Dq / 128, MROWS / 128), 256, GEMM_SMEM_BYTES>>>(
        x_hi, x_lo, wq_hi, wq_lo, b_qkv, qkv, 3 * Dq, Dq);

    // 2. Repack into per-head contiguous q/k/v
    k_repack<<<MROWS, 256>>>();

    // 3. M = K^T V (zero + split-n atomic reduce)
    k_zeroM<<<(BHq * DHq * DHq + 255) / 256, 256>>>();
    k_ktv<<<dim3(BHq, 16), 256>>>();

    // 4. O = Q M -> bf16 hi/lo in 'b n (h d)' layout
    k_qm<<<dim3(BHq, Nq / 128), 256>>>();

    // 5. Output projection (mma.sync bf16x3): out = of @ w_o^T + b_o
    k_gemm_tc<<<dim3(Dq / 128, MROWS / 128), 256, GEMM_SMEM_BYTES>>>(
        of_hi, of_lo, wo_hi, wo_lo, b_o, out, Dq, Dq);
}